// round 7
// baseline (speedup 1.0000x reference)
#include <cuda_runtime.h>

#define N_NODES 100000
#define E_EDGES 1600000
#define INC 128
#define OUTC 64
#define LRELU_ALPHA 0.2f

#define SCAN_B 1024
#define SCAN_NBLK ((N_NODES + SCAN_B - 1) / SCAN_B)   // 98

typedef unsigned long long ull;

#define FMA_F32X2(d, a, b, c) \
    asm("fma.rn.f32x2 %0, %1, %2, %3;" : "=l"(d) : "l"(a), "l"(b), "l"(c))

// Static device scratch (runtime allocation forbidden)
__device__ __align__(16) float g_h[(size_t)N_NODES * OUTC];   // 25.6 MB
__device__ float g_s[N_NODES];
__device__ float g_t[N_NODES];
__device__ int   g_hist[N_NODES];
__device__ int   g_start[N_NODES];
__device__ int   g_cursor[N_NODES];
__device__ int   g_blocksum[SCAN_NBLK];
__device__ int   g_blockoff[SCAN_NBLK];
__device__ __align__(16) int2 g_sorted[E_EDGES];              // (dst, w) 12.8 MB
__device__ int   g_idx64;

// ---------------------------------------------------------------------------
__global__ void detect_zero_kernel(const int* __restrict__ ei32) {
    int i = blockIdx.x * blockDim.x + threadIdx.x;
    if (i < N_NODES) g_hist[i] = 0;
    if (i == 0) {
        int allzero = 1;
#pragma unroll 1
        for (int k = 0; k < 64; ++k)
            if (ei32[2 * k + 1] != 0) { allzero = 0; break; }
        g_idx64 = allzero;
    }
}

// ---------------------------------------------------------------------------
// h = x @ W with packed f32x2 FMAs (W staged in smem), fused s,t projections.
// ---------------------------------------------------------------------------
__global__ __launch_bounds__(256) void gemm_kernel(
    const float* __restrict__ x, const float* __restrict__ W,
    const float* __restrict__ a)
{
    __shared__ __align__(16) float sW[INC * OUTC];   // 32 KB
    {
        const float4* Wv = reinterpret_cast<const float4*>(W);
        float4* sWv = reinterpret_cast<float4*>(sW);
#pragma unroll
        for (int i = 0; i < (INC * OUTC) / (256 * 4); ++i)
            sWv[threadIdx.x + i * 256] = Wv[threadIdx.x + i * 256];
    }
    __syncthreads();

    int row = blockIdx.x * blockDim.x + threadIdx.x;
    if (row >= N_NODES) return;

    ull acc2[OUTC / 2];                 // 32 packed fp32 pairs
#pragma unroll
    for (int c = 0; c < OUTC / 2; ++c) acc2[c] = 0ull;

    const float4* xr = reinterpret_cast<const float4*>(x + (size_t)row * INC);
#pragma unroll 4
    for (int k4 = 0; k4 < INC / 4; ++k4) {
        float4 xv = __ldg(xr + k4);
        float xk[4] = {xv.x, xv.y, xv.z, xv.w};
#pragma unroll
        for (int kk = 0; kk < 4; ++kk) {
            ull xk2;
            asm("mov.b64 %0, {%1, %1};" : "=l"(xk2) : "f"(xk[kk]));
            const ulonglong2* wrow = reinterpret_cast<const ulonglong2*>(
                sW + (k4 * 4 + kk) * OUTC);
#pragma unroll
            for (int c4 = 0; c4 < OUTC / 4; ++c4) {
                ulonglong2 wv = wrow[c4];
                FMA_F32X2(acc2[2 * c4 + 0], xk2, wv.x, acc2[2 * c4 + 0]);
                FMA_F32X2(acc2[2 * c4 + 1], xk2, wv.y, acc2[2 * c4 + 1]);
            }
        }
    }

    // s = h.a[0:64], t = h.a[64:128] with packed FMAs + horizontal add
    const ull* a2 = reinterpret_cast<const ull*>(a);
    ull s2 = 0ull, t2 = 0ull;
#pragma unroll
    for (int c2 = 0; c2 < OUTC / 2; ++c2) {
        FMA_F32X2(s2, acc2[c2], __ldg(a2 + c2), s2);
        FMA_F32X2(t2, acc2[c2], __ldg(a2 + OUTC / 2 + c2), t2);
    }
    float slo, shi, tlo, thi;
    asm("mov.b64 {%0, %1}, %2;" : "=f"(slo), "=f"(shi) : "l"(s2));
    asm("mov.b64 {%0, %1}, %2;" : "=f"(tlo), "=f"(thi) : "l"(t2));
    float s = slo + shi, t = tlo + thi;

    ulonglong2* hp = reinterpret_cast<ulonglong2*>(g_h + (size_t)row * OUTC);
#pragma unroll
    for (int c4 = 0; c4 < OUTC / 4; ++c4)
        hp[c4] = make_ulonglong2(acc2[2 * c4 + 0], acc2[2 * c4 + 1]);
    g_s[row] = s;
    g_t[row] = t;
}

// ---------------------------------------------------------------------------
// Histogram of src: 4 edges per thread.
// ---------------------------------------------------------------------------
__global__ __launch_bounds__(256) void hist_kernel(const void* __restrict__ ei)
{
    int q = blockIdx.x * blockDim.x + threadIdx.x;
    if (q >= E_EDGES / 4) return;
    int s0, s1, s2, s3;
    if (g_idx64) {
        const longlong2* p = (const longlong2*)ei;
        longlong2 a = __ldg(p + 2 * q);
        longlong2 b = __ldg(p + 2 * q + 1);
        s0 = (int)a.x; s1 = (int)a.y; s2 = (int)b.x; s3 = (int)b.y;
    } else {
        int4 v = __ldg((const int4*)ei + q);
        s0 = v.x; s1 = v.y; s2 = v.z; s3 = v.w;
    }
    atomicAdd(g_hist + s0, 1);
    atomicAdd(g_hist + s1, 1);
    atomicAdd(g_hist + s2, 1);
    atomicAdd(g_hist + s3, 1);
}

// ---------------------------------------------------------------------------
__global__ __launch_bounds__(SCAN_B) void scan1_kernel()
{
    __shared__ int sh[SCAN_B];
    int tid = threadIdx.x;
    int i = blockIdx.x * SCAN_B + tid;
    int v = (i < N_NODES) ? g_hist[i] : 0;
    sh[tid] = v;
    __syncthreads();
#pragma unroll
    for (int off = 1; off < SCAN_B; off <<= 1) {
        int t = (tid >= off) ? sh[tid - off] : 0;
        __syncthreads();
        sh[tid] += t;
        __syncthreads();
    }
    if (i < N_NODES) g_start[i] = sh[tid] - v;
    if (tid == SCAN_B - 1) g_blocksum[blockIdx.x] = sh[tid];
}

__global__ void scan2_kernel()
{
    int run = 0;
#pragma unroll 1
    for (int b = 0; b < SCAN_NBLK; ++b) {
        g_blockoff[b] = run;
        run += g_blocksum[b];
    }
}

__global__ __launch_bounds__(SCAN_B) void scan3_kernel()
{
    int i = blockIdx.x * SCAN_B + threadIdx.x;
    if (i < N_NODES) {
        int s = g_start[i] + g_blockoff[blockIdx.x];
        g_start[i] = s;
        g_cursor[i] = s;
    }
}

// ---------------------------------------------------------------------------
// Scatter: 2 edges per thread; packed (dst, w) 8-byte store.
// ---------------------------------------------------------------------------
__global__ __launch_bounds__(256) void scatter_kernel(const void* __restrict__ ei)
{
    int q = blockIdx.x * blockDim.x + threadIdx.x;
    if (q >= E_EDGES / 2) return;
    int src0, src1, dst0, dst1;
    if (g_idx64) {
        const longlong2* p = (const longlong2*)ei;
        longlong2 sv = __ldg(p + q);
        longlong2 dv = __ldg(p + E_EDGES / 2 + q);
        src0 = (int)sv.x; src1 = (int)sv.y;
        dst0 = (int)dv.x; dst1 = (int)dv.y;
    } else {
        const int2* p = (const int2*)ei;
        int2 sv = __ldg(p + q);
        int2 dv = __ldg(p + E_EDGES / 2 + q);
        src0 = sv.x; src1 = sv.y;
        dst0 = dv.x; dst1 = dv.y;
    }

    float z0 = __ldg(g_s + src0) + __ldg(g_t + dst0);
    float z1 = __ldg(g_s + src1) + __ldg(g_t + dst1);
    float w0 = __expf((z0 > 0.0f) ? z0 : LRELU_ALPHA * z0);
    float w1 = __expf((z1 > 0.0f) ? z1 : LRELU_ALPHA * z1);

    int p0 = atomicAdd(g_cursor + src0, 1);
    int p1 = atomicAdd(g_cursor + src1, 1);
    g_sorted[p0] = make_int2(dst0, __float_as_int(w0));
    g_sorted[p1] = make_int2(dst1, __float_as_int(w1));
}

// ---------------------------------------------------------------------------
// Aggregate: 16 lanes per node, 2-edge unrolled for MLP=2 on the h gathers.
// Gather-only; finalize + self-loop fused; single write to d_out.
// ---------------------------------------------------------------------------
__global__ __launch_bounds__(256) void aggregate_kernel(float* __restrict__ out)
{
    int gt = blockIdx.x * blockDim.x + threadIdx.x;
    int node = gt >> 4;
    int sub = gt & 15;
    if (node >= N_NODES) return;

    float z = __ldg(g_s + node) + __ldg(g_t + node);
    float wself = __expf((z > 0.0f) ? z : LRELU_ALPHA * z);

    const float4* hn = reinterpret_cast<const float4*>(g_h + (size_t)node * OUTC);
    float4 hv = __ldg(hn + sub);
    float4 acc = make_float4(wself * hv.x, wself * hv.y, wself * hv.z, wself * hv.w);
    float es = wself;

    int base = __ldg(g_start + node);
    int cnt = __ldg(g_hist + node);

    int j = 0;
#pragma unroll 1
    for (; j + 2 <= cnt; j += 2) {
        int2 m0 = __ldg(g_sorted + base + j);
        int2 m1 = __ldg(g_sorted + base + j + 1);
        const float4* h0 = reinterpret_cast<const float4*>(g_h + (size_t)m0.x * OUTC);
        const float4* h1 = reinterpret_cast<const float4*>(g_h + (size_t)m1.x * OUTC);
        float4 v0 = __ldg(h0 + sub);
        float4 v1 = __ldg(h1 + sub);
        float w0 = __int_as_float(m0.y);
        float w1 = __int_as_float(m1.y);
        acc.x = fmaf(w0, v0.x, acc.x); acc.y = fmaf(w0, v0.y, acc.y);
        acc.z = fmaf(w0, v0.z, acc.z); acc.w = fmaf(w0, v0.w, acc.w);
        acc.x = fmaf(w1, v1.x, acc.x); acc.y = fmaf(w1, v1.y, acc.y);
        acc.z = fmaf(w1, v1.z, acc.z); acc.w = fmaf(w1, v1.w, acc.w);
        es += w0 + w1;
    }
    if (j < cnt) {
        int2 m0 = __ldg(g_sorted + base + j);
        const float4* h0 = reinterpret_cast<const float4*>(g_h + (size_t)m0.x * OUTC);
        float4 v0 = __ldg(h0 + sub);
        float w0 = __int_as_float(m0.y);
        acc.x = fmaf(w0, v0.x, acc.x); acc.y = fmaf(w0, v0.y, acc.y);
        acc.z = fmaf(w0, v0.z, acc.z); acc.w = fmaf(w0, v0.w, acc.w);
        es += w0;
    }

    float inv = 1.0f / es;
    reinterpret_cast<float4*>(out)[(size_t)node * 16 + sub] =
        make_float4(acc.x * inv, acc.y * inv, acc.z * inv, acc.w * inv);
}

// ---------------------------------------------------------------------------
extern "C" void kernel_launch(void* const* d_in, const int* in_sizes, int n_in,
                              void* d_out, int out_size)
{
    const float* x = (const float*)d_in[0];
    const float* W = (const float*)d_in[1];
    const float* a = (const float*)d_in[2];
    const void*  ei = d_in[3];
    float* out = (float*)d_out;

    detect_zero_kernel<<<(N_NODES + 255) / 256, 256>>>((const int*)ei);
    gemm_kernel<<<(N_NODES + 255) / 256, 256>>>(x, W, a);
    hist_kernel<<<(E_EDGES / 4 + 255) / 256, 256>>>(ei);
    scan1_kernel<<<SCAN_NBLK, SCAN_B>>>();
    scan2_kernel<<<1, 1>>>();
    scan3_kernel<<<SCAN_NBLK, SCAN_B>>>();
    scatter_kernel<<<(E_EDGES / 2 + 255) / 256, 256>>>(ei);
    aggregate_kernel<<<(N_NODES * 16 + 255) / 256, 256>>>(out);
}

// round 8
// speedup vs baseline: 1.1781x; 1.1781x over previous
#include <cuda_runtime.h>

#define N_NODES 100000
#define E_EDGES 1600000
#define INC 128
#define OUTC 64
#define LRELU_ALPHA 0.2f

#define SCAN_B 1024
#define SCAN_NBLK ((N_NODES + SCAN_B - 1) / SCAN_B)   // 98

typedef unsigned long long ull;

#define FMA_F32X2(d, a, b, c) \
    asm("fma.rn.f32x2 %0, %1, %2, %3;" : "=l"(d) : "l"(a), "l"(b), "l"(c))

// Static device scratch (runtime allocation forbidden)
__device__ __align__(16) float g_h[(size_t)N_NODES * OUTC];   // 25.6 MB
__device__ float g_s[N_NODES];
__device__ float g_t[N_NODES];
__device__ int   g_hist[N_NODES];
__device__ int   g_start[N_NODES];
__device__ int   g_cursor[N_NODES];
__device__ int   g_blocksum[SCAN_NBLK];
__device__ int   g_blockoff[SCAN_NBLK];
__device__ __align__(16) int2 g_sorted[E_EDGES];              // (dst, w) 12.8 MB
__device__ int   g_idx64;

// ---------------------------------------------------------------------------
__global__ void detect_zero_kernel(const int* __restrict__ ei32) {
    int i = blockIdx.x * blockDim.x + threadIdx.x;
    if (i < N_NODES) g_hist[i] = 0;
    if (i == 0) {
        int allzero = 1;
#pragma unroll 1
        for (int k = 0; k < 64; ++k)
            if (ei32[2 * k + 1] != 0) { allzero = 0; break; }
        g_idx64 = allzero;
    }
}

// ---------------------------------------------------------------------------
// h = x @ W: 2 threads per row, 32 channels each, packed f32x2 FMAs.
// 16 ull accumulators per thread (32 regs) -- no spill pressure.
// s,t projections: partial per half, combined with shfl_xor(1).
// ---------------------------------------------------------------------------
__global__ __launch_bounds__(256) void gemm_kernel(
    const float* __restrict__ x, const float* __restrict__ W,
    const float* __restrict__ a)
{
    __shared__ __align__(16) float sW[INC * OUTC];   // 32 KB
    {
        const float4* Wv = reinterpret_cast<const float4*>(W);
        float4* sWv = reinterpret_cast<float4*>(sW);
#pragma unroll
        for (int i = 0; i < (INC * OUTC) / (256 * 4); ++i)
            sWv[threadIdx.x + i * 256] = Wv[threadIdx.x + i * 256];
    }
    __syncthreads();

    int gt = blockIdx.x * blockDim.x + threadIdx.x;
    int row = gt >> 1;
    int half = gt & 1;              // which 32-channel half
    if (row >= N_NODES) return;

    ull acc2[16];                   // 16 packed fp32 pairs = 32 channels
#pragma unroll
    for (int c = 0; c < 16; ++c) acc2[c] = 0ull;

    const float4* xr = reinterpret_cast<const float4*>(x + (size_t)row * INC);
    const int cbase = half * 32;

#pragma unroll 2
    for (int k4 = 0; k4 < INC / 4; ++k4) {
        float4 xv = __ldg(xr + k4);
        float xk[4] = {xv.x, xv.y, xv.z, xv.w};
#pragma unroll
        for (int kk = 0; kk < 4; ++kk) {
            ull xk2;
            asm("mov.b64 %0, {%1, %1};" : "=l"(xk2) : "f"(xk[kk]));
            const ulonglong2* wrow = reinterpret_cast<const ulonglong2*>(
                sW + (k4 * 4 + kk) * OUTC + cbase);
#pragma unroll
            for (int c4 = 0; c4 < 8; ++c4) {
                ulonglong2 wv = wrow[c4];
                FMA_F32X2(acc2[2 * c4 + 0], xk2, wv.x, acc2[2 * c4 + 0]);
                FMA_F32X2(acc2[2 * c4 + 1], xk2, wv.y, acc2[2 * c4 + 1]);
            }
        }
    }

    // Partial projections over my 32 channels.
    const ull* a2s = reinterpret_cast<const ull*>(a + cbase);
    const ull* a2t = reinterpret_cast<const ull*>(a + OUTC + cbase);
    ull s2 = 0ull, t2 = 0ull;
#pragma unroll
    for (int c2 = 0; c2 < 16; ++c2) {
        FMA_F32X2(s2, acc2[c2], __ldg(a2s + c2), s2);
        FMA_F32X2(t2, acc2[c2], __ldg(a2t + c2), t2);
    }
    float slo, shi, tlo, thi;
    asm("mov.b64 {%0, %1}, %2;" : "=f"(slo), "=f"(shi) : "l"(s2));
    asm("mov.b64 {%0, %1}, %2;" : "=f"(tlo), "=f"(thi) : "l"(t2));
    float s_part = slo + shi, t_part = tlo + thi;

    // Combine halves (adjacent lanes hold the two halves of one row).
    float s = s_part + __shfl_xor_sync(0xFFFFFFFFu, s_part, 1);
    float t = t_part + __shfl_xor_sync(0xFFFFFFFFu, t_part, 1);

    ulonglong2* hp = reinterpret_cast<ulonglong2*>(g_h + (size_t)row * OUTC + cbase);
#pragma unroll
    for (int c4 = 0; c4 < 8; ++c4)
        hp[c4] = make_ulonglong2(acc2[2 * c4 + 0], acc2[2 * c4 + 1]);

    if (half == 0) {
        g_s[row] = s;
        g_t[row] = t;
    }
}

// ---------------------------------------------------------------------------
// Histogram of src: 4 edges per thread.
// ---------------------------------------------------------------------------
__global__ __launch_bounds__(256) void hist_kernel(const void* __restrict__ ei)
{
    int q = blockIdx.x * blockDim.x + threadIdx.x;
    if (q >= E_EDGES / 4) return;
    int s0, s1, s2, s3;
    if (g_idx64) {
        const longlong2* p = (const longlong2*)ei;
        longlong2 a = __ldg(p + 2 * q);
        longlong2 b = __ldg(p + 2 * q + 1);
        s0 = (int)a.x; s1 = (int)a.y; s2 = (int)b.x; s3 = (int)b.y;
    } else {
        int4 v = __ldg((const int4*)ei + q);
        s0 = v.x; s1 = v.y; s2 = v.z; s3 = v.w;
    }
    atomicAdd(g_hist + s0, 1);
    atomicAdd(g_hist + s1, 1);
    atomicAdd(g_hist + s2, 1);
    atomicAdd(g_hist + s3, 1);
}

// ---------------------------------------------------------------------------
__global__ __launch_bounds__(SCAN_B) void scan1_kernel()
{
    __shared__ int sh[SCAN_B];
    int tid = threadIdx.x;
    int i = blockIdx.x * SCAN_B + tid;
    int v = (i < N_NODES) ? g_hist[i] : 0;
    sh[tid] = v;
    __syncthreads();
#pragma unroll
    for (int off = 1; off < SCAN_B; off <<= 1) {
        int t = (tid >= off) ? sh[tid - off] : 0;
        __syncthreads();
        sh[tid] += t;
        __syncthreads();
    }
    if (i < N_NODES) g_start[i] = sh[tid] - v;
    if (tid == SCAN_B - 1) g_blocksum[blockIdx.x] = sh[tid];
}

__global__ void scan2_kernel()
{
    int run = 0;
#pragma unroll 1
    for (int b = 0; b < SCAN_NBLK; ++b) {
        g_blockoff[b] = run;
        run += g_blocksum[b];
    }
}

__global__ __launch_bounds__(SCAN_B) void scan3_kernel()
{
    int i = blockIdx.x * SCAN_B + threadIdx.x;
    if (i < N_NODES) {
        int s = g_start[i] + g_blockoff[blockIdx.x];
        g_start[i] = s;
        g_cursor[i] = s;
    }
}

// ---------------------------------------------------------------------------
// Scatter: 2 edges per thread; packed (dst, w) 8-byte store.
// ---------------------------------------------------------------------------
__global__ __launch_bounds__(256) void scatter_kernel(const void* __restrict__ ei)
{
    int q = blockIdx.x * blockDim.x + threadIdx.x;
    if (q >= E_EDGES / 2) return;
    int src0, src1, dst0, dst1;
    if (g_idx64) {
        const longlong2* p = (const longlong2*)ei;
        longlong2 sv = __ldg(p + q);
        longlong2 dv = __ldg(p + E_EDGES / 2 + q);
        src0 = (int)sv.x; src1 = (int)sv.y;
        dst0 = (int)dv.x; dst1 = (int)dv.y;
    } else {
        const int2* p = (const int2*)ei;
        int2 sv = __ldg(p + q);
        int2 dv = __ldg(p + E_EDGES / 2 + q);
        src0 = sv.x; src1 = sv.y;
        dst0 = dv.x; dst1 = dv.y;
    }

    float z0 = __ldg(g_s + src0) + __ldg(g_t + dst0);
    float z1 = __ldg(g_s + src1) + __ldg(g_t + dst1);
    float w0 = __expf((z0 > 0.0f) ? z0 : LRELU_ALPHA * z0);
    float w1 = __expf((z1 > 0.0f) ? z1 : LRELU_ALPHA * z1);

    int p0 = atomicAdd(g_cursor + src0, 1);
    int p1 = atomicAdd(g_cursor + src1, 1);
    g_sorted[p0] = make_int2(dst0, __float_as_int(w0));
    g_sorted[p1] = make_int2(dst1, __float_as_int(w1));
}

// ---------------------------------------------------------------------------
// Aggregate: 16 lanes per node, 2-edge unrolled (MLP=2 on h gathers).
// ---------------------------------------------------------------------------
__global__ __launch_bounds__(256) void aggregate_kernel(float* __restrict__ out)
{
    int gt = blockIdx.x * blockDim.x + threadIdx.x;
    int node = gt >> 4;
    int sub = gt & 15;
    if (node >= N_NODES) return;

    float z = __ldg(g_s + node) + __ldg(g_t + node);
    float wself = __expf((z > 0.0f) ? z : LRELU_ALPHA * z);

    const float4* hn = reinterpret_cast<const float4*>(g_h + (size_t)node * OUTC);
    float4 hv = __ldg(hn + sub);
    float4 acc = make_float4(wself * hv.x, wself * hv.y, wself * hv.z, wself * hv.w);
    float es = wself;

    int base = __ldg(g_start + node);
    int cnt = __ldg(g_hist + node);

    int j = 0;
#pragma unroll 1
    for (; j + 2 <= cnt; j += 2) {
        int2 m0 = __ldg(g_sorted + base + j);
        int2 m1 = __ldg(g_sorted + base + j + 1);
        const float4* h0 = reinterpret_cast<const float4*>(g_h + (size_t)m0.x * OUTC);
        const float4* h1 = reinterpret_cast<const float4*>(g_h + (size_t)m1.x * OUTC);
        float4 v0 = __ldg(h0 + sub);
        float4 v1 = __ldg(h1 + sub);
        float w0 = __int_as_float(m0.y);
        float w1 = __int_as_float(m1.y);
        acc.x = fmaf(w0, v0.x, acc.x); acc.y = fmaf(w0, v0.y, acc.y);
        acc.z = fmaf(w0, v0.z, acc.z); acc.w = fmaf(w0, v0.w, acc.w);
        acc.x = fmaf(w1, v1.x, acc.x); acc.y = fmaf(w1, v1.y, acc.y);
        acc.z = fmaf(w1, v1.z, acc.z); acc.w = fmaf(w1, v1.w, acc.w);
        es += w0 + w1;
    }
    if (j < cnt) {
        int2 m0 = __ldg(g_sorted + base + j);
        const float4* h0 = reinterpret_cast<const float4*>(g_h + (size_t)m0.x * OUTC);
        float4 v0 = __ldg(h0 + sub);
        float w0 = __int_as_float(m0.y);
        acc.x = fmaf(w0, v0.x, acc.x); acc.y = fmaf(w0, v0.y, acc.y);
        acc.z = fmaf(w0, v0.z, acc.z); acc.w = fmaf(w0, v0.w, acc.w);
        es += w0;
    }

    float inv = 1.0f / es;
    reinterpret_cast<float4*>(out)[(size_t)node * 16 + sub] =
        make_float4(acc.x * inv, acc.y * inv, acc.z * inv, acc.w * inv);
}

// ---------------------------------------------------------------------------
extern "C" void kernel_launch(void* const* d_in, const int* in_sizes, int n_in,
                              void* d_out, int out_size)
{
    const float* x = (const float*)d_in[0];
    const float* W = (const float*)d_in[1];
    const float* a = (const float*)d_in[2];
    const void*  ei = d_in[3];
    float* out = (float*)d_out;

    detect_zero_kernel<<<(N_NODES + 255) / 256, 256>>>((const int*)ei);
    gemm_kernel<<<(N_NODES * 2 + 255) / 256, 256>>>(x, W, a);
    hist_kernel<<<(E_EDGES / 4 + 255) / 256, 256>>>(ei);
    scan1_kernel<<<SCAN_NBLK, SCAN_B>>>();
    scan2_kernel<<<1, 1>>>();
    scan3_kernel<<<SCAN_NBLK, SCAN_B>>>();
    scatter_kernel<<<(E_EDGES / 2 + 255) / 256, 256>>>(ei);
    aggregate_kernel<<<(N_NODES * 16 + 255) / 256, 256>>>(out);
}

// round 9
// speedup vs baseline: 1.4580x; 1.2375x over previous
#include <cuda_runtime.h>

#define N_NODES 100000
#define E_EDGES 1600000
#define INC 128
#define OUTC 64
#define LRELU_ALPHA 0.2f

#define SCAN_B 1024
#define SCAN_NBLK ((N_NODES + SCAN_B - 1) / SCAN_B)   // 98

// Static device scratch (runtime allocation forbidden)
__device__ __align__(16) float g_h[(size_t)N_NODES * OUTC];   // 25.6 MB
__device__ float g_s[N_NODES];
__device__ float g_t[N_NODES];
__device__ int   g_hist[N_NODES];
__device__ int   g_start[N_NODES];
__device__ int   g_cursor[N_NODES];
__device__ int   g_blocksum[SCAN_NBLK];
__device__ int   g_blockoff[SCAN_NBLK];
__device__ __align__(16) int2 g_sorted[E_EDGES];              // (dst, w) 12.8 MB
__device__ int   g_idx64;

// ---------------------------------------------------------------------------
__global__ void detect_zero_kernel(const int* __restrict__ ei32) {
    int i = blockIdx.x * blockDim.x + threadIdx.x;
    if (i < N_NODES) g_hist[i] = 0;
    if (i == 0) {
        int allzero = 1;
#pragma unroll 1
        for (int k = 0; k < 64; ++k)
            if (ei32[2 * k + 1] != 0) { allzero = 0; break; }
        g_idx64 = allzero;
    }
}

// ---------------------------------------------------------------------------
// h = x @ W (scalar FFMA, W staged in smem), fused s,t projections.
// (Proven R6 version -- f32x2 experiments regressed twice.)
// ---------------------------------------------------------------------------
__global__ __launch_bounds__(256) void gemm_kernel(
    const float* __restrict__ x, const float* __restrict__ W,
    const float* __restrict__ a)
{
    __shared__ __align__(16) float sW[INC * OUTC];   // 32 KB
    {
        const float4* Wv = reinterpret_cast<const float4*>(W);
        float4* sWv = reinterpret_cast<float4*>(sW);
#pragma unroll
        for (int i = 0; i < (INC * OUTC) / (256 * 4); ++i)
            sWv[threadIdx.x + i * 256] = Wv[threadIdx.x + i * 256];
    }
    __syncthreads();

    int row = blockIdx.x * blockDim.x + threadIdx.x;
    if (row >= N_NODES) return;

    float acc[OUTC];
#pragma unroll
    for (int c = 0; c < OUTC; ++c) acc[c] = 0.0f;

    const float4* xr = reinterpret_cast<const float4*>(x + (size_t)row * INC);
#pragma unroll 2
    for (int k4 = 0; k4 < INC / 4; ++k4) {
        float4 xv = __ldg(xr + k4);
        float xk[4] = {xv.x, xv.y, xv.z, xv.w};
#pragma unroll
        for (int kk = 0; kk < 4; ++kk) {
            const float4* w4 =
                reinterpret_cast<const float4*>(sW + (k4 * 4 + kk) * OUTC);
#pragma unroll
            for (int c4 = 0; c4 < OUTC / 4; ++c4) {
                float4 wv = w4[c4];
                acc[c4 * 4 + 0] = fmaf(xk[kk], wv.x, acc[c4 * 4 + 0]);
                acc[c4 * 4 + 1] = fmaf(xk[kk], wv.y, acc[c4 * 4 + 1]);
                acc[c4 * 4 + 2] = fmaf(xk[kk], wv.z, acc[c4 * 4 + 2]);
                acc[c4 * 4 + 3] = fmaf(xk[kk], wv.w, acc[c4 * 4 + 3]);
            }
        }
    }

    float s = 0.0f, t = 0.0f;
#pragma unroll
    for (int c = 0; c < OUTC; ++c) {
        s = fmaf(acc[c], __ldg(a + c), s);
        t = fmaf(acc[c], __ldg(a + OUTC + c), t);
    }

    float4* hp = reinterpret_cast<float4*>(g_h + (size_t)row * OUTC);
#pragma unroll
    for (int c4 = 0; c4 < OUTC / 4; ++c4)
        hp[c4] = make_float4(acc[c4 * 4 + 0], acc[c4 * 4 + 1],
                             acc[c4 * 4 + 2], acc[c4 * 4 + 3]);
    g_s[row] = s;
    g_t[row] = t;
}

// ---------------------------------------------------------------------------
// Histogram of src: 4 edges per thread.
// ---------------------------------------------------------------------------
__global__ __launch_bounds__(256) void hist_kernel(const void* __restrict__ ei)
{
    int q = blockIdx.x * blockDim.x + threadIdx.x;
    if (q >= E_EDGES / 4) return;
    int s0, s1, s2, s3;
    if (g_idx64) {
        const longlong2* p = (const longlong2*)ei;
        longlong2 a = __ldg(p + 2 * q);
        longlong2 b = __ldg(p + 2 * q + 1);
        s0 = (int)a.x; s1 = (int)a.y; s2 = (int)b.x; s3 = (int)b.y;
    } else {
        int4 v = __ldg((const int4*)ei + q);
        s0 = v.x; s1 = v.y; s2 = v.z; s3 = v.w;
    }
    atomicAdd(g_hist + s0, 1);
    atomicAdd(g_hist + s1, 1);
    atomicAdd(g_hist + s2, 1);
    atomicAdd(g_hist + s3, 1);
}

// ---------------------------------------------------------------------------
__global__ __launch_bounds__(SCAN_B) void scan1_kernel()
{
    __shared__ int sh[SCAN_B];
    int tid = threadIdx.x;
    int i = blockIdx.x * SCAN_B + tid;
    int v = (i < N_NODES) ? g_hist[i] : 0;
    sh[tid] = v;
    __syncthreads();
#pragma unroll
    for (int off = 1; off < SCAN_B; off <<= 1) {
        int t = (tid >= off) ? sh[tid - off] : 0;
        __syncthreads();
        sh[tid] += t;
        __syncthreads();
    }
    if (i < N_NODES) g_start[i] = sh[tid] - v;
    if (tid == SCAN_B - 1) g_blocksum[blockIdx.x] = sh[tid];
}

__global__ void scan2_kernel()
{
    int run = 0;
#pragma unroll 1
    for (int b = 0; b < SCAN_NBLK; ++b) {
        g_blockoff[b] = run;
        run += g_blocksum[b];
    }
}

__global__ __launch_bounds__(SCAN_B) void scan3_kernel()
{
    int i = blockIdx.x * SCAN_B + threadIdx.x;
    if (i < N_NODES) {
        int s = g_start[i] + g_blockoff[blockIdx.x];
        g_start[i] = s;
        g_cursor[i] = s;
    }
}

// ---------------------------------------------------------------------------
// Scatter: 2 edges per thread; packed (dst, w) 8-byte store.
// ---------------------------------------------------------------------------
__global__ __launch_bounds__(256) void scatter_kernel(const void* __restrict__ ei)
{
    int q = blockIdx.x * blockDim.x + threadIdx.x;
    if (q >= E_EDGES / 2) return;
    int src0, src1, dst0, dst1;
    if (g_idx64) {
        const longlong2* p = (const longlong2*)ei;
        longlong2 sv = __ldg(p + q);
        longlong2 dv = __ldg(p + E_EDGES / 2 + q);
        src0 = (int)sv.x; src1 = (int)sv.y;
        dst0 = (int)dv.x; dst1 = (int)dv.y;
    } else {
        const int2* p = (const int2*)ei;
        int2 sv = __ldg(p + q);
        int2 dv = __ldg(p + E_EDGES / 2 + q);
        src0 = sv.x; src1 = sv.y;
        dst0 = dv.x; dst1 = dv.y;
    }

    float z0 = __ldg(g_s + src0) + __ldg(g_t + dst0);
    float z1 = __ldg(g_s + src1) + __ldg(g_t + dst1);
    float w0 = __expf((z0 > 0.0f) ? z0 : LRELU_ALPHA * z0);
    float w1 = __expf((z1 > 0.0f) ? z1 : LRELU_ALPHA * z1);

    int p0 = atomicAdd(g_cursor + src0, 1);
    int p1 = atomicAdd(g_cursor + src1, 1);
    g_sorted[p0] = make_int2(dst0, __float_as_int(w0));
    g_sorted[p1] = make_int2(dst1, __float_as_int(w1));
}

// ---------------------------------------------------------------------------
// Aggregate: ONE WARP PER NODE. Lanes split into two halves (h = lane>>4);
// per iteration each half gathers up to 2 edges (predicated) -> 4 independent
// float4 gathers in flight per warp, no cross-node divergence.
// Final cross-half combine via shfl_xor(16); half 0 writes d_out.
// ---------------------------------------------------------------------------
__global__ __launch_bounds__(256) void aggregate_kernel(float* __restrict__ out)
{
    int warp = (blockIdx.x * blockDim.x + threadIdx.x) >> 5;
    if (warp >= N_NODES) return;
    int node = warp;
    int lane = threadIdx.x & 31;
    int h = lane >> 4;            // half id (0/1)
    int sub = lane & 15;          // float4 index within 64-ch row

    // self-loop (half 0 only, to avoid double count)
    float z = __ldg(g_s + node) + __ldg(g_t + node);
    float wself = __expf((z > 0.0f) ? z : LRELU_ALPHA * z);

    const float4* hn = reinterpret_cast<const float4*>(g_h + (size_t)node * OUTC);
    float4 acc = make_float4(0.f, 0.f, 0.f, 0.f);
    float es = 0.0f;
    if (h == 0) {
        float4 hv = __ldg(hn + sub);
        acc = make_float4(wself * hv.x, wself * hv.y, wself * hv.z, wself * hv.w);
        es = wself;
    }

    int base = __ldg(g_start + node);
    int cnt = __ldg(g_hist + node);

#pragma unroll 1
    for (int j = 0; j < cnt; j += 4) {
        int k0 = j + h;           // this half's first edge
        int k1 = j + 2 + h;       // this half's second edge
        bool p0 = k0 < cnt;
        bool p1 = k1 < cnt;
        int2 m0 = p0 ? __ldg(g_sorted + base + k0) : make_int2(0, 0);
        int2 m1 = p1 ? __ldg(g_sorted + base + k1) : make_int2(0, 0);
        if (p0) {
            const float4* h0 = reinterpret_cast<const float4*>(g_h + (size_t)m0.x * OUTC);
            float4 v0 = __ldg(h0 + sub);
            float w0 = __int_as_float(m0.y);
            acc.x = fmaf(w0, v0.x, acc.x); acc.y = fmaf(w0, v0.y, acc.y);
            acc.z = fmaf(w0, v0.z, acc.z); acc.w = fmaf(w0, v0.w, acc.w);
            es += w0;
        }
        if (p1) {
            const float4* h1 = reinterpret_cast<const float4*>(g_h + (size_t)m1.x * OUTC);
            float4 v1 = __ldg(h1 + sub);
            float w1 = __int_as_float(m1.y);
            acc.x = fmaf(w1, v1.x, acc.x); acc.y = fmaf(w1, v1.y, acc.y);
            acc.z = fmaf(w1, v1.z, acc.z); acc.w = fmaf(w1, v1.w, acc.w);
            es += w1;
        }
    }

    // combine the two halves (same sub lives at lane ^ 16)
    acc.x += __shfl_xor_sync(0xFFFFFFFFu, acc.x, 16);
    acc.y += __shfl_xor_sync(0xFFFFFFFFu, acc.y, 16);
    acc.z += __shfl_xor_sync(0xFFFFFFFFu, acc.z, 16);
    acc.w += __shfl_xor_sync(0xFFFFFFFFu, acc.w, 16);
    es    += __shfl_xor_sync(0xFFFFFFFFu, es, 16);

    if (h == 0) {
        float inv = 1.0f / es;
        reinterpret_cast<float4*>(out)[(size_t)node * 16 + sub] =
            make_float4(acc.x * inv, acc.y * inv, acc.z * inv, acc.w * inv);
    }
}

// ---------------------------------------------------------------------------
extern "C" void kernel_launch(void* const* d_in, const int* in_sizes, int n_in,
                              void* d_out, int out_size)
{
    const float* x = (const float*)d_in[0];
    const float* W = (const float*)d_in[1];
    const float* a = (const float*)d_in[2];
    const void*  ei = d_in[3];
    float* out = (float*)d_out;

    detect_zero_kernel<<<(N_NODES + 255) / 256, 256>>>((const int*)ei);
    gemm_kernel<<<(N_NODES + 255) / 256, 256>>>(x, W, a);
    hist_kernel<<<(E_EDGES / 4 + 255) / 256, 256>>>(ei);
    scan1_kernel<<<SCAN_NBLK, SCAN_B>>>();
    scan2_kernel<<<1, 1>>>();
    scan3_kernel<<<SCAN_NBLK, SCAN_B>>>();
    scatter_kernel<<<(E_EDGES / 2 + 255) / 256, 256>>>(ei);
    aggregate_kernel<<<(N_NODES * 32 + 255) / 256, 256>>>(out);
}

// round 10
// speedup vs baseline: 1.5465x; 1.0607x over previous
#include <cuda_runtime.h>
#include <cuda_fp16.h>

#define N_NODES 100000
#define E_EDGES 1600000
#define INC 128
#define OUTC 64
#define LRELU_ALPHA 0.2f

#define SCAN_B 1024
#define SCAN_NBLK ((N_NODES + SCAN_B - 1) / SCAN_B)   // 98

// Static device scratch (runtime allocation forbidden)
__device__ __align__(16) __half g_h[(size_t)N_NODES * OUTC];  // 12.8 MB (fp16)
__device__ float g_s[N_NODES];
__device__ float g_t[N_NODES];
__device__ int   g_hist[N_NODES];
__device__ int   g_start[N_NODES];
__device__ int   g_cursor[N_NODES];
__device__ int   g_blocksum[SCAN_NBLK];
__device__ int   g_blockoff[SCAN_NBLK];
__device__ __align__(16) int2 g_sorted[E_EDGES];              // (dst, w) 12.8 MB
__device__ int   g_idx64;

// ---------------------------------------------------------------------------
__global__ void detect_zero_kernel(const int* __restrict__ ei32) {
    int i = blockIdx.x * blockDim.x + threadIdx.x;
    if (i < N_NODES) g_hist[i] = 0;
    if (i == 0) {
        int allzero = 1;
#pragma unroll 1
        for (int k = 0; k < 64; ++k)
            if (ei32[2 * k + 1] != 0) { allzero = 0; break; }
        g_idx64 = allzero;
    }
}

// ---------------------------------------------------------------------------
// h = x @ W (scalar FFMA in fp32, W staged in smem), fused s,t projections
// (fp32). h stored to global as fp16 (consumed only by the aggregate gather).
// ---------------------------------------------------------------------------
__global__ __launch_bounds__(256) void gemm_kernel(
    const float* __restrict__ x, const float* __restrict__ W,
    const float* __restrict__ a)
{
    __shared__ __align__(16) float sW[INC * OUTC];   // 32 KB
    {
        const float4* Wv = reinterpret_cast<const float4*>(W);
        float4* sWv = reinterpret_cast<float4*>(sW);
#pragma unroll
        for (int i = 0; i < (INC * OUTC) / (256 * 4); ++i)
            sWv[threadIdx.x + i * 256] = Wv[threadIdx.x + i * 256];
    }
    __syncthreads();

    int row = blockIdx.x * blockDim.x + threadIdx.x;
    if (row >= N_NODES) return;

    float acc[OUTC];
#pragma unroll
    for (int c = 0; c < OUTC; ++c) acc[c] = 0.0f;

    const float4* xr = reinterpret_cast<const float4*>(x + (size_t)row * INC);
#pragma unroll 2
    for (int k4 = 0; k4 < INC / 4; ++k4) {
        float4 xv = __ldg(xr + k4);
        float xk[4] = {xv.x, xv.y, xv.z, xv.w};
#pragma unroll
        for (int kk = 0; kk < 4; ++kk) {
            const float4* w4 =
                reinterpret_cast<const float4*>(sW + (k4 * 4 + kk) * OUTC);
#pragma unroll
            for (int c4 = 0; c4 < OUTC / 4; ++c4) {
                float4 wv = w4[c4];
                acc[c4 * 4 + 0] = fmaf(xk[kk], wv.x, acc[c4 * 4 + 0]);
                acc[c4 * 4 + 1] = fmaf(xk[kk], wv.y, acc[c4 * 4 + 1]);
                acc[c4 * 4 + 2] = fmaf(xk[kk], wv.z, acc[c4 * 4 + 2]);
                acc[c4 * 4 + 3] = fmaf(xk[kk], wv.w, acc[c4 * 4 + 3]);
            }
        }
    }

    float s = 0.0f, t = 0.0f;
#pragma unroll
    for (int c = 0; c < OUTC; ++c) {
        s = fmaf(acc[c], __ldg(a + c), s);
        t = fmaf(acc[c], __ldg(a + OUTC + c), t);
    }

    // Pack 64 fp32 -> 32 half2 -> 8 uint4 stores (128B row).
    uint4* hp = reinterpret_cast<uint4*>(g_h + (size_t)row * OUTC);
#pragma unroll
    for (int g = 0; g < 8; ++g) {
        __half2 p0 = __floats2half2_rn(acc[8 * g + 0], acc[8 * g + 1]);
        __half2 p1 = __floats2half2_rn(acc[8 * g + 2], acc[8 * g + 3]);
        __half2 p2 = __floats2half2_rn(acc[8 * g + 4], acc[8 * g + 5]);
        __half2 p3 = __floats2half2_rn(acc[8 * g + 6], acc[8 * g + 7]);
        uint4 u;
        u.x = *reinterpret_cast<unsigned*>(&p0);
        u.y = *reinterpret_cast<unsigned*>(&p1);
        u.z = *reinterpret_cast<unsigned*>(&p2);
        u.w = *reinterpret_cast<unsigned*>(&p3);
        hp[g] = u;
    }
    g_s[row] = s;
    g_t[row] = t;
}

// ---------------------------------------------------------------------------
// Histogram of src: 4 edges per thread.
// ---------------------------------------------------------------------------
__global__ __launch_bounds__(256) void hist_kernel(const void* __restrict__ ei)
{
    int q = blockIdx.x * blockDim.x + threadIdx.x;
    if (q >= E_EDGES / 4) return;
    int s0, s1, s2, s3;
    if (g_idx64) {
        const longlong2* p = (const longlong2*)ei;
        longlong2 a = __ldg(p + 2 * q);
        longlong2 b = __ldg(p + 2 * q + 1);
        s0 = (int)a.x; s1 = (int)a.y; s2 = (int)b.x; s3 = (int)b.y;
    } else {
        int4 v = __ldg((const int4*)ei + q);
        s0 = v.x; s1 = v.y; s2 = v.z; s3 = v.w;
    }
    atomicAdd(g_hist + s0, 1);
    atomicAdd(g_hist + s1, 1);
    atomicAdd(g_hist + s2, 1);
    atomicAdd(g_hist + s3, 1);
}

// ---------------------------------------------------------------------------
__global__ __launch_bounds__(SCAN_B) void scan1_kernel()
{
    __shared__ int sh[SCAN_B];
    int tid = threadIdx.x;
    int i = blockIdx.x * SCAN_B + tid;
    int v = (i < N_NODES) ? g_hist[i] : 0;
    sh[tid] = v;
    __syncthreads();
#pragma unroll
    for (int off = 1; off < SCAN_B; off <<= 1) {
        int t = (tid >= off) ? sh[tid - off] : 0;
        __syncthreads();
        sh[tid] += t;
        __syncthreads();
    }
    if (i < N_NODES) g_start[i] = sh[tid] - v;
    if (tid == SCAN_B - 1) g_blocksum[blockIdx.x] = sh[tid];
}

__global__ void scan2_kernel()
{
    int run = 0;
#pragma unroll 1
    for (int b = 0; b < SCAN_NBLK; ++b) {
        g_blockoff[b] = run;
        run += g_blocksum[b];
    }
}

__global__ __launch_bounds__(SCAN_B) void scan3_kernel()
{
    int i = blockIdx.x * SCAN_B + threadIdx.x;
    if (i < N_NODES) {
        int s = g_start[i] + g_blockoff[blockIdx.x];
        g_start[i] = s;
        g_cursor[i] = s;
    }
}

// ---------------------------------------------------------------------------
// Scatter: 2 edges per thread; packed (dst, w) 8-byte store.
// ---------------------------------------------------------------------------
__global__ __launch_bounds__(256) void scatter_kernel(const void* __restrict__ ei)
{
    int q = blockIdx.x * blockDim.x + threadIdx.x;
    if (q >= E_EDGES / 2) return;
    int src0, src1, dst0, dst1;
    if (g_idx64) {
        const longlong2* p = (const longlong2*)ei;
        longlong2 sv = __ldg(p + q);
        longlong2 dv = __ldg(p + E_EDGES / 2 + q);
        src0 = (int)sv.x; src1 = (int)sv.y;
        dst0 = (int)dv.x; dst1 = (int)dv.y;
    } else {
        const int2* p = (const int2*)ei;
        int2 sv = __ldg(p + q);
        int2 dv = __ldg(p + E_EDGES / 2 + q);
        src0 = sv.x; src1 = sv.y;
        dst0 = dv.x; dst1 = dv.y;
    }

    float z0 = __ldg(g_s + src0) + __ldg(g_t + dst0);
    float z1 = __ldg(g_s + src1) + __ldg(g_t + dst1);
    float w0 = __expf((z0 > 0.0f) ? z0 : LRELU_ALPHA * z0);
    float w1 = __expf((z1 > 0.0f) ? z1 : LRELU_ALPHA * z1);

    int p0 = atomicAdd(g_cursor + src0, 1);
    int p1 = atomicAdd(g_cursor + src1, 1);
    g_sorted[p0] = make_int2(dst0, __float_as_int(w0));
    g_sorted[p1] = make_int2(dst1, __float_as_int(w1));
}

// ---------------------------------------------------------------------------
// Aggregate: 16 lanes per node; each lane owns 4 channels (uint2 = 4 halves
// per gather -> 128B coalesced row). fp32 accumulation; 2-edge unroll;
// finalize + self-loop fused; single float4 write to d_out.
// ---------------------------------------------------------------------------
__device__ __forceinline__ float4 h4_load(int nodeid, int sub) {
    uint2 u = __ldg(reinterpret_cast<const uint2*>(g_h + (size_t)nodeid * OUTC) + sub);
    __half2 p0 = *reinterpret_cast<__half2*>(&u.x);
    __half2 p1 = *reinterpret_cast<__half2*>(&u.y);
    float2 f0 = __half22float2(p0);
    float2 f1 = __half22float2(p1);
    return make_float4(f0.x, f0.y, f1.x, f1.y);
}

__global__ __launch_bounds__(256) void aggregate_kernel(float* __restrict__ out)
{
    int gt = blockIdx.x * blockDim.x + threadIdx.x;
    int node = gt >> 4;
    int sub = gt & 15;
    if (node >= N_NODES) return;

    float z = __ldg(g_s + node) + __ldg(g_t + node);
    float wself = __expf((z > 0.0f) ? z : LRELU_ALPHA * z);

    float4 hv = h4_load(node, sub);
    float4 acc = make_float4(wself * hv.x, wself * hv.y, wself * hv.z, wself * hv.w);
    float es = wself;

    int base = __ldg(g_start + node);
    int cnt = __ldg(g_hist + node);

    int j = 0;
#pragma unroll 1
    for (; j + 2 <= cnt; j += 2) {
        int2 m0 = __ldg(g_sorted + base + j);
        int2 m1 = __ldg(g_sorted + base + j + 1);
        float4 v0 = h4_load(m0.x, sub);
        float4 v1 = h4_load(m1.x, sub);
        float w0 = __int_as_float(m0.y);
        float w1 = __int_as_float(m1.y);
        acc.x = fmaf(w0, v0.x, acc.x); acc.y = fmaf(w0, v0.y, acc.y);
        acc.z = fmaf(w0, v0.z, acc.z); acc.w = fmaf(w0, v0.w, acc.w);
        acc.x = fmaf(w1, v1.x, acc.x); acc.y = fmaf(w1, v1.y, acc.y);
        acc.z = fmaf(w1, v1.z, acc.z); acc.w = fmaf(w1, v1.w, acc.w);
        es += w0 + w1;
    }
    if (j < cnt) {
        int2 m0 = __ldg(g_sorted + base + j);
        float4 v0 = h4_load(m0.x, sub);
        float w0 = __int_as_float(m0.y);
        acc.x = fmaf(w0, v0.x, acc.x); acc.y = fmaf(w0, v0.y, acc.y);
        acc.z = fmaf(w0, v0.z, acc.z); acc.w = fmaf(w0, v0.w, acc.w);
        es += w0;
    }

    float inv = 1.0f / es;
    reinterpret_cast<float4*>(out)[(size_t)node * 16 + sub] =
        make_float4(acc.x * inv, acc.y * inv, acc.z * inv, acc.w * inv);
}

// ---------------------------------------------------------------------------
extern "C" void kernel_launch(void* const* d_in, const int* in_sizes, int n_in,
                              void* d_out, int out_size)
{
    const float* x = (const float*)d_in[0];
    const float* W = (const float*)d_in[1];
    const float* a = (const float*)d_in[2];
    const void*  ei = d_in[3];
    float* out = (float*)d_out;

    detect_zero_kernel<<<(N_NODES + 255) / 256, 256>>>((const int*)ei);
    gemm_kernel<<<(N_NODES + 255) / 256, 256>>>(x, W, a);
    hist_kernel<<<(E_EDGES / 4 + 255) / 256, 256>>>(ei);
    scan1_kernel<<<SCAN_NBLK, SCAN_B>>>();
    scan2_kernel<<<1, 1>>>();
    scan3_kernel<<<SCAN_NBLK, SCAN_B>>>();
    scatter_kernel<<<(E_EDGES / 2 + 255) / 256, 256>>>(ei);
    aggregate_kernel<<<(N_NODES * 16 + 255) / 256, 256>>>(out);
}

// round 11
// speedup vs baseline: 1.9141x; 1.2377x over previous
#include <cuda_runtime.h>
#include <cuda_fp16.h>

#define N_NODES 100000
#define E_EDGES 1600000
#define INC 128
#define OUTC 64
#define LRELU_ALPHA 0.2f

#define SCAN_B 1024
#define SCAN_NBLK ((N_NODES + SCAN_B - 1) / SCAN_B)   // 98

// GEMM tiling
#define MBLK 64                      // rows per block
#define GEMM_THREADS 128             // 4 warps, 16 rows each
#define XS 136                       // padded smem row stride (halves)

// Static device scratch (runtime allocation forbidden)
__device__ __align__(16) __half g_h[(size_t)N_NODES * OUTC];  // 12.8 MB (fp16)
__device__ float g_s[N_NODES];
__device__ float g_t[N_NODES];
__device__ float g_p[INC];           // W @ a1
__device__ float g_q[INC];           // W @ a2
__device__ int   g_hist[N_NODES];
__device__ int   g_start[N_NODES];
__device__ int   g_cursor[N_NODES];
__device__ int   g_blocksum[SCAN_NBLK];
__device__ int   g_blockoff[SCAN_NBLK];
__device__ __align__(16) int2 g_sorted[E_EDGES];              // (dst, w) 12.8 MB
__device__ int   g_idx64;

// ---------------------------------------------------------------------------
// p = W @ a1, q = W @ a2 (tiny, fp32) -- lets gemm compute s,t as x.p / x.q.
// ---------------------------------------------------------------------------
__global__ void pq_kernel(const float* __restrict__ W, const float* __restrict__ a)
{
    int k = threadIdx.x;
    if (k >= INC) return;
    float p = 0.0f, q = 0.0f;
#pragma unroll 8
    for (int c = 0; c < OUTC; ++c) {
        float wv = __ldg(W + k * OUTC + c);
        p = fmaf(wv, __ldg(a + c), p);
        q = fmaf(wv, __ldg(a + OUTC + c), q);
    }
    g_p[k] = p;
    g_q[k] = q;
}

// ---------------------------------------------------------------------------
__global__ void detect_zero_kernel(const int* __restrict__ ei32) {
    int i = blockIdx.x * blockDim.x + threadIdx.x;
    if (i < N_NODES) g_hist[i] = 0;
    if (i == 0) {
        int allzero = 1;
#pragma unroll 1
        for (int k = 0; k < 64; ++k)
            if (ei32[2 * k + 1] != 0) { allzero = 0; break; }
        g_idx64 = allzero;
    }
}

// ---------------------------------------------------------------------------
// h = x @ W via fp16 HMMA (mma.sync.m16n8k16, fp32 accum). s,t computed in
// fp32 from x.p / x.q during the x-tile load (protects the exp path).
// ---------------------------------------------------------------------------
__global__ __launch_bounds__(GEMM_THREADS) void gemm_kernel(
    const float* __restrict__ x, const float* __restrict__ W)
{
    __shared__ __align__(16) __half x_sh[MBLK * XS];    // 17408 B
    __shared__ __align__(16) __half w_sh[OUTC * XS];    // 17408 B (W^T: [n][k])

    int tid = threadIdx.x;
    int lane = tid & 31;
    int warp = tid >> 5;
    int rowbase = blockIdx.x * MBLK;

    // --- Load W (k-major [128][64] fp32) transposed into w_sh[n][k] fp16 ---
    {
        int n = tid & 63;
        int k0 = tid >> 6;          // 0 or 1
#pragma unroll 16
        for (int j = 0; j < 64; ++j) {
            int k = k0 + 2 * j;
            w_sh[n * XS + k] = __float2half_rn(__ldg(W + k * OUTC + n));
        }
    }

    // --- Load x tile (fp32 -> fp16 smem) + fused fp32 s,t partials ---
    {
        int r = tid >> 1;
        int hf = tid & 1;
        int grow = rowbase + r;
        float sp = 0.0f, tp = 0.0f;
        uint2* xsh2 = reinterpret_cast<uint2*>(x_sh);
        const float4* xr = reinterpret_cast<const float4*>(x) +
                           (size_t)grow * (INC / 4) + hf * 16;
        const float4* p4 = reinterpret_cast<const float4*>(g_p) + hf * 16;
        const float4* q4 = reinterpret_cast<const float4*>(g_q) + hf * 16;
        bool valid = grow < N_NODES;
#pragma unroll 4
        for (int i = 0; i < 16; ++i) {
            float4 xv = valid ? __ldg(xr + i) : make_float4(0.f, 0.f, 0.f, 0.f);
            float4 pv = __ldg(p4 + i);
            float4 qv = __ldg(q4 + i);
            sp = fmaf(xv.x, pv.x, sp); sp = fmaf(xv.y, pv.y, sp);
            sp = fmaf(xv.z, pv.z, sp); sp = fmaf(xv.w, pv.w, sp);
            tp = fmaf(xv.x, qv.x, tp); tp = fmaf(xv.y, qv.y, tp);
            tp = fmaf(xv.z, qv.z, tp); tp = fmaf(xv.w, qv.w, tp);
            __half2 h0 = __floats2half2_rn(xv.x, xv.y);
            __half2 h1 = __floats2half2_rn(xv.z, xv.w);
            uint2 u;
            u.x = *reinterpret_cast<unsigned*>(&h0);
            u.y = *reinterpret_cast<unsigned*>(&h1);
            xsh2[34 * r + 16 * hf + i] = u;
        }
        float s = sp + __shfl_xor_sync(0xFFFFFFFFu, sp, 1);
        float t = tp + __shfl_xor_sync(0xFFFFFFFFu, tp, 1);
        if (hf == 0 && valid) {
            g_s[grow] = s;
            g_t[grow] = t;
        }
    }
    __syncthreads();

    // --- MMA mainloop: warp computes rows [warp*16, warp*16+16) x 64 cols ---
    int g = lane >> 2;
    int t4 = lane & 3;
    const unsigned* xs32 = reinterpret_cast<const unsigned*>(x_sh);
    const unsigned* ws32 = reinterpret_cast<const unsigned*>(w_sh);

    float d[8][4];
#pragma unroll
    for (int nt = 0; nt < 8; ++nt)
#pragma unroll
        for (int i = 0; i < 4; ++i) d[nt][i] = 0.0f;

#pragma unroll
    for (int ks = 0; ks < 8; ++ks) {
        int r0 = warp * 16 + g;
        unsigned a0 = xs32[r0 * 68 + ks * 8 + t4];
        unsigned a1 = xs32[(r0 + 8) * 68 + ks * 8 + t4];
        unsigned a2 = xs32[r0 * 68 + ks * 8 + t4 + 4];
        unsigned a3 = xs32[(r0 + 8) * 68 + ks * 8 + t4 + 4];
#pragma unroll
        for (int nt = 0; nt < 8; ++nt) {
            int n = nt * 8 + g;
            unsigned b0 = ws32[n * 68 + ks * 8 + t4];
            unsigned b1 = ws32[n * 68 + ks * 8 + t4 + 4];
            asm volatile(
                "mma.sync.aligned.m16n8k16.row.col.f32.f16.f16.f32 "
                "{%0,%1,%2,%3},{%4,%5,%6,%7},{%8,%9},{%0,%1,%2,%3};"
                : "+f"(d[nt][0]), "+f"(d[nt][1]), "+f"(d[nt][2]), "+f"(d[nt][3])
                : "r"(a0), "r"(a1), "r"(a2), "r"(a3), "r"(b0), "r"(b1));
        }
    }

    // --- Epilogue: store h as fp16 (half2 per fragment pair) ---
    __half2* gh2 = reinterpret_cast<__half2*>(g_h);
    int row0 = rowbase + warp * 16 + g;
    int row1 = row0 + 8;
#pragma unroll
    for (int nt = 0; nt < 8; ++nt) {
        if (row0 < N_NODES)
            gh2[(size_t)row0 * 32 + nt * 4 + t4] = __floats2half2_rn(d[nt][0], d[nt][1]);
        if (row1 < N_NODES)
            gh2[(size_t)row1 * 32 + nt * 4 + t4] = __floats2half2_rn(d[nt][2], d[nt][3]);
    }
}

// ---------------------------------------------------------------------------
// Histogram of src: 4 edges per thread.
// ---------------------------------------------------------------------------
__global__ __launch_bounds__(256) void hist_kernel(const void* __restrict__ ei)
{
    int q = blockIdx.x * blockDim.x + threadIdx.x;
    if (q >= E_EDGES / 4) return;
    int s0, s1, s2, s3;
    if (g_idx64) {
        const longlong2* p = (const longlong2*)ei;
        longlong2 a = __ldg(p + 2 * q);
        longlong2 b = __ldg(p + 2 * q + 1);
        s0 = (int)a.x; s1 = (int)a.y; s2 = (int)b.x; s3 = (int)b.y;
    } else {
        int4 v = __ldg((const int4*)ei + q);
        s0 = v.x; s1 = v.y; s2 = v.z; s3 = v.w;
    }
    atomicAdd(g_hist + s0, 1);
    atomicAdd(g_hist + s1, 1);
    atomicAdd(g_hist + s2, 1);
    atomicAdd(g_hist + s3, 1);
}

// ---------------------------------------------------------------------------
__global__ __launch_bounds__(SCAN_B) void scan1_kernel()
{
    __shared__ int sh[SCAN_B];
    int tid = threadIdx.x;
    int i = blockIdx.x * SCAN_B + tid;
    int v = (i < N_NODES) ? g_hist[i] : 0;
    sh[tid] = v;
    __syncthreads();
#pragma unroll
    for (int off = 1; off < SCAN_B; off <<= 1) {
        int t = (tid >= off) ? sh[tid - off] : 0;
        __syncthreads();
        sh[tid] += t;
        __syncthreads();
    }
    if (i < N_NODES) g_start[i] = sh[tid] - v;
    if (tid == SCAN_B - 1) g_blocksum[blockIdx.x] = sh[tid];
}

__global__ void scan2_kernel()
{
    int run = 0;
#pragma unroll 1
    for (int b = 0; b < SCAN_NBLK; ++b) {
        g_blockoff[b] = run;
        run += g_blocksum[b];
    }
}

__global__ __launch_bounds__(SCAN_B) void scan3_kernel()
{
    int i = blockIdx.x * SCAN_B + threadIdx.x;
    if (i < N_NODES) {
        int s = g_start[i] + g_blockoff[blockIdx.x];
        g_start[i] = s;
        g_cursor[i] = s;
    }
}

// ---------------------------------------------------------------------------
// Scatter: 2 edges per thread; packed (dst, w) 8-byte store.
// ---------------------------------------------------------------------------
__global__ __launch_bounds__(256) void scatter_kernel(const void* __restrict__ ei)
{
    int q = blockIdx.x * blockDim.x + threadIdx.x;
    if (q >= E_EDGES / 2) return;
    int src0, src1, dst0, dst1;
    if (g_idx64) {
        const longlong2* p = (const longlong2*)ei;
        longlong2 sv = __ldg(p + q);
        longlong2 dv = __ldg(p + E_EDGES / 2 + q);
        src0 = (int)sv.x; src1 = (int)sv.y;
        dst0 = (int)dv.x; dst1 = (int)dv.y;
    } else {
        const int2* p = (const int2*)ei;
        int2 sv = __ldg(p + q);
        int2 dv = __ldg(p + E_EDGES / 2 + q);
        src0 = sv.x; src1 = sv.y;
        dst0 = dv.x; dst1 = dv.y;
    }

    float z0 = __ldg(g_s + src0) + __ldg(g_t + dst0);
    float z1 = __ldg(g_s + src1) + __ldg(g_t + dst1);
    float w0 = __expf((z0 > 0.0f) ? z0 : LRELU_ALPHA * z0);
    float w1 = __expf((z1 > 0.0f) ? z1 : LRELU_ALPHA * z1);

    int p0 = atomicAdd(g_cursor + src0, 1);
    int p1 = atomicAdd(g_cursor + src1, 1);
    g_sorted[p0] = make_int2(dst0, __float_as_int(w0));
    g_sorted[p1] = make_int2(dst1, __float_as_int(w1));
}

// ---------------------------------------------------------------------------
// Aggregate: 16 lanes per node; fp16 h gathers (uint2 = 4 halves / lane);
// fp32 accumulation; 2-edge unroll; finalize + self-loop fused.
// ---------------------------------------------------------------------------
__device__ __forceinline__ float4 h4_load(int nodeid, int sub) {
    uint2 u = __ldg(reinterpret_cast<const uint2*>(g_h + (size_t)nodeid * OUTC) + sub);
    __half2 p0 = *reinterpret_cast<__half2*>(&u.x);
    __half2 p1 = *reinterpret_cast<__half2*>(&u.y);
    float2 f0 = __half22float2(p0);
    float2 f1 = __half22float2(p1);
    return make_float4(f0.x, f0.y, f1.x, f1.y);
}

__global__ __launch_bounds__(256) void aggregate_kernel(float* __restrict__ out)
{
    int gt = blockIdx.x * blockDim.x + threadIdx.x;
    int node = gt >> 4;
    int sub = gt & 15;
    if (node >= N_NODES) return;

    float z = __ldg(g_s + node) + __ldg(g_t + node);
    float wself = __expf((z > 0.0f) ? z : LRELU_ALPHA * z);

    float4 hv = h4_load(node, sub);
    float4 acc = make_float4(wself * hv.x, wself * hv.y, wself * hv.z, wself * hv.w);
    float es = wself;

    int base = __ldg(g_start + node);
    int cnt = __ldg(g_hist + node);

    int j = 0;
#pragma unroll 1
    for (; j + 2 <= cnt; j += 2) {
        int2 m0 = __ldg(g_sorted + base + j);
        int2 m1 = __ldg(g_sorted + base + j + 1);
        float4 v0 = h4_load(m0.x, sub);
        float4 v1 = h4_load(m1.x, sub);
        float w0 = __int_as_float(m0.y);
        float w1 = __int_as_float(m1.y);
        acc.x = fmaf(w0, v0.x, acc.x); acc.y = fmaf(w0, v0.y, acc.y);
        acc.z = fmaf(w0, v0.z, acc.z); acc.w = fmaf(w0, v0.w, acc.w);
        acc.x = fmaf(w1, v1.x, acc.x); acc.y = fmaf(w1, v1.y, acc.y);
        acc.z = fmaf(w1, v1.z, acc.z); acc.w = fmaf(w1, v1.w, acc.w);
        es += w0 + w1;
    }
    if (j < cnt) {
        int2 m0 = __ldg(g_sorted + base + j);
        float4 v0 = h4_load(m0.x, sub);
        float w0 = __int_as_float(m0.y);
        acc.x = fmaf(w0, v0.x, acc.x); acc.y = fmaf(w0, v0.y, acc.y);
        acc.z = fmaf(w0, v0.z, acc.z); acc.w = fmaf(w0, v0.w, acc.w);
        es += w0;
    }

    float inv = 1.0f / es;
    reinterpret_cast<float4*>(out)[(size_t)node * 16 + sub] =
        make_float4(acc.x * inv, acc.y * inv, acc.z * inv, acc.w * inv);
}

// ---------------------------------------------------------------------------
extern "C" void kernel_launch(void* const* d_in, const int* in_sizes, int n_in,
                              void* d_out, int out_size)
{
    const float* x = (const float*)d_in[0];
    const float* W = (const float*)d_in[1];
    const float* a = (const float*)d_in[2];
    const void*  ei = d_in[3];
    float* out = (float*)d_out;

    // Order chosen so the 6th launch (ncu -s 5 -c 1) is the gemm.
    pq_kernel<<<1, 128>>>(W, a);
    detect_zero_kernel<<<(N_NODES + 255) / 256, 256>>>((const int*)ei);
    hist_kernel<<<(E_EDGES / 4 + 255) / 256, 256>>>(ei);
    scan1_kernel<<<SCAN_NBLK, SCAN_B>>>();
    scan2_kernel<<<1, 1>>>();
    gemm_kernel<<<(N_NODES + MBLK - 1) / MBLK, GEMM_THREADS>>>(x, W);
    scan3_kernel<<<SCAN_NBLK, SCAN_B>>>();
    scatter_kernel<<<(E_EDGES / 2 + 255) / 256, 256>>>(ei);
    aggregate_kernel<<<(N_NODES * 16 + 255) / 256, 256>>>(out);
}

// round 12
// speedup vs baseline: 2.0348x; 1.0630x over previous
#include <cuda_runtime.h>
#include <cuda_fp16.h>

#define N_NODES 100000
#define E_EDGES 1600000
#define INC 128
#define OUTC 64
#define LRELU_ALPHA 0.2f

#define SCAN_B 1024
#define SCAN_NBLK ((N_NODES + SCAN_B - 1) / SCAN_B)   // 98

// GEMM tiling
#define MBLK 64                      // rows per block
#define GEMM_THREADS 128             // 4 warps, 16 rows each
#define XS 136                       // padded smem row stride (halves)

// Static device scratch (runtime allocation forbidden)
__device__ __align__(16) __half g_h[(size_t)N_NODES * OUTC];  // 12.8 MB (fp16)
__device__ float g_s[N_NODES];
__device__ float g_t[N_NODES];
__device__ float g_p[INC];           // W @ a1
__device__ float g_q[INC];           // W @ a2
__device__ int   g_hist[N_NODES];
__device__ int   g_start[N_NODES];
__device__ int   g_blocksum[SCAN_NBLK];
__device__ int   g_blockoff[SCAN_NBLK];
__device__ __align__(16) int2 g_sorted[E_EDGES];              // (dst, w) 12.8 MB
__device__ int   g_idx64;

// ---------------------------------------------------------------------------
// p = W @ a1, q = W @ a2 (tiny, fp32).
// ---------------------------------------------------------------------------
__global__ void pq_kernel(const float* __restrict__ W, const float* __restrict__ a)
{
    int k = threadIdx.x;
    if (k >= INC) return;
    float p = 0.0f, q = 0.0f;
#pragma unroll 8
    for (int c = 0; c < OUTC; ++c) {
        float wv = __ldg(W + k * OUTC + c);
        p = fmaf(wv, __ldg(a + c), p);
        q = fmaf(wv, __ldg(a + OUTC + c), q);
    }
    g_p[k] = p;
    g_q[k] = q;
}

// ---------------------------------------------------------------------------
__global__ void detect_zero_kernel(const int* __restrict__ ei32) {
    int i = blockIdx.x * blockDim.x + threadIdx.x;
    if (i < N_NODES) g_hist[i] = 0;
    if (i == 0) {
        int allzero = 1;
#pragma unroll 1
        for (int k = 0; k < 64; ++k)
            if (ei32[2 * k + 1] != 0) { allzero = 0; break; }
        g_idx64 = allzero;
    }
}

// ---------------------------------------------------------------------------
// h = x @ W via fp16 HMMA (fp32 accum) + fused fp32 s,t + FUSED HISTOGRAM.
// ---------------------------------------------------------------------------
__global__ __launch_bounds__(GEMM_THREADS) void gemm_kernel(
    const float* __restrict__ x, const float* __restrict__ W,
    const void* __restrict__ ei)
{
    __shared__ __align__(16) __half x_sh[MBLK * XS];    // 17408 B
    __shared__ __align__(16) __half w_sh[OUTC * XS];    // 17408 B (W^T: [n][k])

    int tid = threadIdx.x;
    int lane = tid & 31;
    int warp = tid >> 5;
    int rowbase = blockIdx.x * MBLK;

    // --- Load W (k-major [128][64] fp32) transposed into w_sh[n][k] fp16 ---
    {
        int n = tid & 63;
        int k0 = tid >> 6;          // 0 or 1
#pragma unroll 16
        for (int j = 0; j < 64; ++j) {
            int k = k0 + 2 * j;
            w_sh[n * XS + k] = __float2half_rn(__ldg(W + k * OUTC + n));
        }
    }

    // --- Load x tile (fp32 -> fp16 smem) + fused fp32 s,t partials ---
    {
        int r = tid >> 1;
        int hf = tid & 1;
        int grow = rowbase + r;
        float sp = 0.0f, tp = 0.0f;
        uint2* xsh2 = reinterpret_cast<uint2*>(x_sh);
        const float4* xr = reinterpret_cast<const float4*>(x) +
                           (size_t)grow * (INC / 4) + hf * 16;
        const float4* p4 = reinterpret_cast<const float4*>(g_p) + hf * 16;
        const float4* q4 = reinterpret_cast<const float4*>(g_q) + hf * 16;
        bool valid = grow < N_NODES;
#pragma unroll 4
        for (int i = 0; i < 16; ++i) {
            float4 xv = valid ? __ldg(xr + i) : make_float4(0.f, 0.f, 0.f, 0.f);
            float4 pv = __ldg(p4 + i);
            float4 qv = __ldg(q4 + i);
            sp = fmaf(xv.x, pv.x, sp); sp = fmaf(xv.y, pv.y, sp);
            sp = fmaf(xv.z, pv.z, sp); sp = fmaf(xv.w, pv.w, sp);
            tp = fmaf(xv.x, qv.x, tp); tp = fmaf(xv.y, qv.y, tp);
            tp = fmaf(xv.z, qv.z, tp); tp = fmaf(xv.w, qv.w, tp);
            __half2 h0 = __floats2half2_rn(xv.x, xv.y);
            __half2 h1 = __floats2half2_rn(xv.z, xv.w);
            uint2 u;
            u.x = *reinterpret_cast<unsigned*>(&h0);
            u.y = *reinterpret_cast<unsigned*>(&h1);
            xsh2[34 * r + 16 * hf + i] = u;
        }
        float s = sp + __shfl_xor_sync(0xFFFFFFFFu, sp, 1);
        float t = tp + __shfl_xor_sync(0xFFFFFFFFu, tp, 1);
        if (hf == 0 && valid) {
            g_s[grow] = s;
            g_t[grow] = t;
        }
    }
    __syncthreads();

    // --- MMA mainloop ---
    int g = lane >> 2;
    int t4 = lane & 3;
    const unsigned* xs32 = reinterpret_cast<const unsigned*>(x_sh);
    const unsigned* ws32 = reinterpret_cast<const unsigned*>(w_sh);

    float d[8][4];
#pragma unroll
    for (int nt = 0; nt < 8; ++nt)
#pragma unroll
        for (int i = 0; i < 4; ++i) d[nt][i] = 0.0f;

#pragma unroll
    for (int ks = 0; ks < 8; ++ks) {
        int r0 = warp * 16 + g;
        unsigned a0 = xs32[r0 * 68 + ks * 8 + t4];
        unsigned a1 = xs32[(r0 + 8) * 68 + ks * 8 + t4];
        unsigned a2 = xs32[r0 * 68 + ks * 8 + t4 + 4];
        unsigned a3 = xs32[(r0 + 8) * 68 + ks * 8 + t4 + 4];
#pragma unroll
        for (int nt = 0; nt < 8; ++nt) {
            int n = nt * 8 + g;
            unsigned b0 = ws32[n * 68 + ks * 8 + t4];
            unsigned b1 = ws32[n * 68 + ks * 8 + t4 + 4];
            asm volatile(
                "mma.sync.aligned.m16n8k16.row.col.f32.f16.f16.f32 "
                "{%0,%1,%2,%3},{%4,%5,%6,%7},{%8,%9},{%0,%1,%2,%3};"
                : "+f"(d[nt][0]), "+f"(d[nt][1]), "+f"(d[nt][2]), "+f"(d[nt][3])
                : "r"(a0), "r"(a1), "r"(a2), "r"(a3), "r"(b0), "r"(b1));
        }
    }

    // --- Epilogue: store h as fp16 ---
    __half2* gh2 = reinterpret_cast<__half2*>(g_h);
    int row0 = rowbase + warp * 16 + g;
    int row1 = row0 + 8;
#pragma unroll
    for (int nt = 0; nt < 8; ++nt) {
        if (row0 < N_NODES)
            gh2[(size_t)row0 * 32 + nt * 4 + t4] = __floats2half2_rn(d[nt][0], d[nt][1]);
        if (row1 < N_NODES)
            gh2[(size_t)row1 * 32 + nt * 4 + t4] = __floats2half2_rn(d[nt][2], d[nt][3]);
    }

    // --- Fused histogram of src (4 edges per quad; grid-stride) ---
    {
        int gt = blockIdx.x * GEMM_THREADS + tid;
        int nthreads = gridDim.x * GEMM_THREADS;
        if (g_idx64) {
            const longlong2* p = (const longlong2*)ei;
#pragma unroll 1
            for (int q = gt; q < E_EDGES / 4; q += nthreads) {
                longlong2 a0 = __ldg(p + 2 * q);
                longlong2 b0 = __ldg(p + 2 * q + 1);
                atomicAdd(g_hist + (int)a0.x, 1);
                atomicAdd(g_hist + (int)a0.y, 1);
                atomicAdd(g_hist + (int)b0.x, 1);
                atomicAdd(g_hist + (int)b0.y, 1);
            }
        } else {
            const int4* p = (const int4*)ei;
#pragma unroll 1
            for (int q = gt; q < E_EDGES / 4; q += nthreads) {
                int4 v = __ldg(p + q);
                atomicAdd(g_hist + v.x, 1);
                atomicAdd(g_hist + v.y, 1);
                atomicAdd(g_hist + v.z, 1);
                atomicAdd(g_hist + v.w, 1);
            }
        }
    }
}

// ---------------------------------------------------------------------------
// Scan step 1: per-block exclusive scan of hist into g_start (block-local).
// ---------------------------------------------------------------------------
__global__ __launch_bounds__(SCAN_B) void scan1_kernel()
{
    __shared__ int sh[SCAN_B];
    int tid = threadIdx.x;
    int i = blockIdx.x * SCAN_B + tid;
    int v = (i < N_NODES) ? g_hist[i] : 0;
    sh[tid] = v;
    __syncthreads();
#pragma unroll
    for (int off = 1; off < SCAN_B; off <<= 1) {
        int t = (tid >= off) ? sh[tid - off] : 0;
        __syncthreads();
        sh[tid] += t;
        __syncthreads();
    }
    if (i < N_NODES) g_start[i] = sh[tid] - v;
    if (tid == SCAN_B - 1) g_blocksum[blockIdx.x] = sh[tid];
}

__global__ void scan2_kernel()
{
    int run = 0;
#pragma unroll 1
    for (int b = 0; b < SCAN_NBLK; ++b) {
        g_blockoff[b] = run;
        run += g_blocksum[b];
    }
}

// ---------------------------------------------------------------------------
// Scatter: 2 edges/thread. Position = atomicAdd(g_start[src]) + blockoff.
// (scan3/cursor eliminated; scan1 rewrites g_start each replay.)
// ---------------------------------------------------------------------------
__global__ __launch_bounds__(256) void scatter_kernel(const void* __restrict__ ei)
{
    int q = blockIdx.x * blockDim.x + threadIdx.x;
    if (q >= E_EDGES / 2) return;
    int src0, src1, dst0, dst1;
    if (g_idx64) {
        const longlong2* p = (const longlong2*)ei;
        longlong2 sv = __ldg(p + q);
        longlong2 dv = __ldg(p + E_EDGES / 2 + q);
        src0 = (int)sv.x; src1 = (int)sv.y;
        dst0 = (int)dv.x; dst1 = (int)dv.y;
    } else {
        const int2* p = (const int2*)ei;
        int2 sv = __ldg(p + q);
        int2 dv = __ldg(p + E_EDGES / 2 + q);
        src0 = sv.x; src1 = sv.y;
        dst0 = dv.x; dst1 = dv.y;
    }

    float z0 = __ldg(g_s + src0) + __ldg(g_t + dst0);
    float z1 = __ldg(g_s + src1) + __ldg(g_t + dst1);
    float w0 = __expf((z0 > 0.0f) ? z0 : LRELU_ALPHA * z0);
    float w1 = __expf((z1 > 0.0f) ? z1 : LRELU_ALPHA * z1);

    int p0 = atomicAdd(g_start + src0, 1) + __ldg(g_blockoff + (src0 >> 10));
    int p1 = atomicAdd(g_start + src1, 1) + __ldg(g_blockoff + (src1 >> 10));
    g_sorted[p0] = make_int2(dst0, __float_as_int(w0));
    g_sorted[p1] = make_int2(dst1, __float_as_int(w1));
}

// ---------------------------------------------------------------------------
// Aggregate: 16 lanes per node; fp16 h gathers; fp32 accum; 2-edge unroll.
// base = g_start (post-scatter = local_excl + cnt) + blockoff - cnt.
// ---------------------------------------------------------------------------
__device__ __forceinline__ float4 h4_load(int nodeid, int sub) {
    uint2 u = __ldg(reinterpret_cast<const uint2*>(g_h + (size_t)nodeid * OUTC) + sub);
    __half2 p0 = *reinterpret_cast<__half2*>(&u.x);
    __half2 p1 = *reinterpret_cast<__half2*>(&u.y);
    float2 f0 = __half22float2(p0);
    float2 f1 = __half22float2(p1);
    return make_float4(f0.x, f0.y, f1.x, f1.y);
}

__global__ __launch_bounds__(256) void aggregate_kernel(float* __restrict__ out)
{
    int gt = blockIdx.x * blockDim.x + threadIdx.x;
    int node = gt >> 4;
    int sub = gt & 15;
    if (node >= N_NODES) return;

    float z = __ldg(g_s + node) + __ldg(g_t + node);
    float wself = __expf((z > 0.0f) ? z : LRELU_ALPHA * z);

    float4 hv = h4_load(node, sub);
    float4 acc = make_float4(wself * hv.x, wself * hv.y, wself * hv.z, wself * hv.w);
    float es = wself;

    int cnt = __ldg(g_hist + node);
    int base = __ldg(g_start + node) + __ldg(g_blockoff + (node >> 10)) - cnt;

    int j = 0;
#pragma unroll 1
    for (; j + 2 <= cnt; j += 2) {
        int2 m0 = __ldg(g_sorted + base + j);
        int2 m1 = __ldg(g_sorted + base + j + 1);
        float4 v0 = h4_load(m0.x, sub);
        float4 v1 = h4_load(m1.x, sub);
        float w0 = __int_as_float(m0.y);
        float w1 = __int_as_float(m1.y);
        acc.x = fmaf(w0, v0.x, acc.x); acc.y = fmaf(w0, v0.y, acc.y);
        acc.z = fmaf(w0, v0.z, acc.z); acc.w = fmaf(w0, v0.w, acc.w);
        acc.x = fmaf(w1, v1.x, acc.x); acc.y = fmaf(w1, v1.y, acc.y);
        acc.z = fmaf(w1, v1.z, acc.z); acc.w = fmaf(w1, v1.w, acc.w);
        es += w0 + w1;
    }
    if (j < cnt) {
        int2 m0 = __ldg(g_sorted + base + j);
        float4 v0 = h4_load(m0.x, sub);
        float w0 = __int_as_float(m0.y);
        acc.x = fmaf(w0, v0.x, acc.x); acc.y = fmaf(w0, v0.y, acc.y);
        acc.z = fmaf(w0, v0.z, acc.z); acc.w = fmaf(w0, v0.w, acc.w);
        es += w0;
    }

    float inv = 1.0f / es;
    reinterpret_cast<float4*>(out)[(size_t)node * 16 + sub] =
        make_float4(acc.x * inv, acc.y * inv, acc.z * inv, acc.w * inv);
}

// ---------------------------------------------------------------------------
extern "C" void kernel_launch(void* const* d_in, const int* in_sizes, int n_in,
                              void* d_out, int out_size)
{
    const float* x = (const float*)d_in[0];
    const float* W = (const float*)d_in[1];
    const float* a = (const float*)d_in[2];
    const void*  ei = d_in[3];
    float* out = (float*)d_out;

    pq_kernel<<<1, 128>>>(W, a);
    detect_zero_kernel<<<(N_NODES + 255) / 256, 256>>>((const int*)ei);
    gemm_kernel<<<(N_NODES + MBLK - 1) / MBLK, GEMM_THREADS>>>(x, W, ei);
    scan1_kernel<<<SCAN_NBLK, SCAN_B>>>();
    scan2_kernel<<<1, 1>>>();
    scatter_kernel<<<(E_EDGES / 2 + 255) / 256, 256>>>(ei);
    aggregate_kernel<<<(N_NODES * 16 + 255) / 256, 256>>>(out);
}

// round 13
// speedup vs baseline: 2.1286x; 1.0461x over previous
#include <cuda_runtime.h>
#include <cuda_fp16.h>

#define N_NODES 100000
#define E_EDGES 1600000
#define INC 128
#define OUTC 64
#define LRELU_ALPHA 0.2f

#define SCAN_B 1024
#define SCAN_NBLK ((N_NODES + SCAN_B - 1) / SCAN_B)   // 98

// GEMM tiling
#define MBLK 64
#define GEMM_THREADS 128
#define XS 136

// Static device scratch (runtime allocation forbidden)
__device__ __align__(16) __half g_h[(size_t)N_NODES * OUTC];  // 12.8 MB (fp16)
__device__ float g_s[N_NODES];
__device__ float g_t[N_NODES];
__device__ float g_p[INC];
__device__ float g_q[INC];
__device__ int   g_hist[N_NODES];
__device__ int   g_start[N_NODES];
__device__ int   g_blocksum[SCAN_NBLK];
__device__ int   g_blockoff[SCAN_NBLK];
__device__ __align__(16) int2 g_sorted[E_EDGES];              // 12.8 MB
__device__ int   g_idx64;

// ---------------------------------------------------------------------------
__global__ void pq_kernel(const float* __restrict__ W, const float* __restrict__ a)
{
    int k = threadIdx.x;
    if (k >= INC) return;
    float p = 0.0f, q = 0.0f;
#pragma unroll 8
    for (int c = 0; c < OUTC; ++c) {
        float wv = __ldg(W + k * OUTC + c);
        p = fmaf(wv, __ldg(a + c), p);
        q = fmaf(wv, __ldg(a + OUTC + c), q);
    }
    g_p[k] = p;
    g_q[k] = q;
}

// ---------------------------------------------------------------------------
__global__ void detect_zero_kernel(const int* __restrict__ ei32) {
    int i = blockIdx.x * blockDim.x + threadIdx.x;
    if (i < N_NODES) g_hist[i] = 0;
    if (i == 0) {
        int allzero = 1;
#pragma unroll 1
        for (int k = 0; k < 64; ++k)
            if (ei32[2 * k + 1] != 0) { allzero = 0; break; }
        g_idx64 = allzero;
    }
}

// ---------------------------------------------------------------------------
// h = x @ W via fp16 HMMA (fp32 accum); fused fp32 s,t (x.p / x.q).
// ---------------------------------------------------------------------------
__global__ __launch_bounds__(GEMM_THREADS) void gemm_kernel(
    const float* __restrict__ x, const float* __restrict__ W)
{
    __shared__ __align__(16) __half x_sh[MBLK * XS];
    __shared__ __align__(16) __half w_sh[OUTC * XS];

    int tid = threadIdx.x;
    int lane = tid & 31;
    int warp = tid >> 5;
    int rowbase = blockIdx.x * MBLK;

    {
        int n = tid & 63;
        int k0 = tid >> 6;
#pragma unroll 16
        for (int j = 0; j < 64; ++j) {
            int k = k0 + 2 * j;
            w_sh[n * XS + k] = __float2half_rn(__ldg(W + k * OUTC + n));
        }
    }

    {
        int r = tid >> 1;
        int hf = tid & 1;
        int grow = rowbase + r;
        float sp = 0.0f, tp = 0.0f;
        uint2* xsh2 = reinterpret_cast<uint2*>(x_sh);
        const float4* xr = reinterpret_cast<const float4*>(x) +
                           (size_t)grow * (INC / 4) + hf * 16;
        const float4* p4 = reinterpret_cast<const float4*>(g_p) + hf * 16;
        const float4* q4 = reinterpret_cast<const float4*>(g_q) + hf * 16;
        bool valid = grow < N_NODES;
#pragma unroll 4
        for (int i = 0; i < 16; ++i) {
            float4 xv = valid ? __ldg(xr + i) : make_float4(0.f, 0.f, 0.f, 0.f);
            float4 pv = __ldg(p4 + i);
            float4 qv = __ldg(q4 + i);
            sp = fmaf(xv.x, pv.x, sp); sp = fmaf(xv.y, pv.y, sp);
            sp = fmaf(xv.z, pv.z, sp); sp = fmaf(xv.w, pv.w, sp);
            tp = fmaf(xv.x, qv.x, tp); tp = fmaf(xv.y, qv.y, tp);
            tp = fmaf(xv.z, qv.z, tp); tp = fmaf(xv.w, qv.w, tp);
            __half2 h0 = __floats2half2_rn(xv.x, xv.y);
            __half2 h1 = __floats2half2_rn(xv.z, xv.w);
            uint2 u;
            u.x = *reinterpret_cast<unsigned*>(&h0);
            u.y = *reinterpret_cast<unsigned*>(&h1);
            xsh2[34 * r + 16 * hf + i] = u;
        }
        float s = sp + __shfl_xor_sync(0xFFFFFFFFu, sp, 1);
        float t = tp + __shfl_xor_sync(0xFFFFFFFFu, tp, 1);
        if (hf == 0 && valid) {
            g_s[grow] = s;
            g_t[grow] = t;
        }
    }
    __syncthreads();

    int g = lane >> 2;
    int t4 = lane & 3;
    const unsigned* xs32 = reinterpret_cast<const unsigned*>(x_sh);
    const unsigned* ws32 = reinterpret_cast<const unsigned*>(w_sh);

    float d[8][4];
#pragma unroll
    for (int nt = 0; nt < 8; ++nt)
#pragma unroll
        for (int i = 0; i < 4; ++i) d[nt][i] = 0.0f;

#pragma unroll
    for (int ks = 0; ks < 8; ++ks) {
        int r0 = warp * 16 + g;
        unsigned a0 = xs32[r0 * 68 + ks * 8 + t4];
        unsigned a1 = xs32[(r0 + 8) * 68 + ks * 8 + t4];
        unsigned a2 = xs32[r0 * 68 + ks * 8 + t4 + 4];
        unsigned a3 = xs32[(r0 + 8) * 68 + ks * 8 + t4 + 4];
#pragma unroll
        for (int nt = 0; nt < 8; ++nt) {
            int n = nt * 8 + g;
            unsigned b0 = ws32[n * 68 + ks * 8 + t4];
            unsigned b1 = ws32[n * 68 + ks * 8 + t4 + 4];
            asm volatile(
                "mma.sync.aligned.m16n8k16.row.col.f32.f16.f16.f32 "
                "{%0,%1,%2,%3},{%4,%5,%6,%7},{%8,%9},{%0,%1,%2,%3};"
                : "+f"(d[nt][0]), "+f"(d[nt][1]), "+f"(d[nt][2]), "+f"(d[nt][3])
                : "r"(a0), "r"(a1), "r"(a2), "r"(a3), "r"(b0), "r"(b1));
        }
    }

    __half2* gh2 = reinterpret_cast<__half2*>(g_h);
    int row0 = rowbase + warp * 16 + g;
    int row1 = row0 + 8;
#pragma unroll
    for (int nt = 0; nt < 8; ++nt) {
        if (row0 < N_NODES)
            gh2[(size_t)row0 * 32 + nt * 4 + t4] = __floats2half2_rn(d[nt][0], d[nt][1]);
        if (row1 < N_NODES)
            gh2[(size_t)row1 * 32 + nt * 4 + t4] = __floats2half2_rn(d[nt][2], d[nt][3]);
    }
}

// ---------------------------------------------------------------------------
__global__ __launch_bounds__(256) void hist_kernel(const void* __restrict__ ei)
{
    int q = blockIdx.x * blockDim.x + threadIdx.x;
    if (q >= E_EDGES / 4) return;
    int s0, s1, s2, s3;
    if (g_idx64) {
        const longlong2* p = (const longlong2*)ei;
        longlong2 a = __ldg(p + 2 * q);
        longlong2 b = __ldg(p + 2 * q + 1);
        s0 = (int)a.x; s1 = (int)a.y; s2 = (int)b.x; s3 = (int)b.y;
    } else {
        int4 v = __ldg((const int4*)ei + q);
        s0 = v.x; s1 = v.y; s2 = v.z; s3 = v.w;
    }
    atomicAdd(g_hist + s0, 1);
    atomicAdd(g_hist + s1, 1);
    atomicAdd(g_hist + s2, 1);
    atomicAdd(g_hist + s3, 1);
}

// ---------------------------------------------------------------------------
__global__ __launch_bounds__(SCAN_B) void scan1_kernel()
{
    __shared__ int sh[SCAN_B];
    int tid = threadIdx.x;
    int i = blockIdx.x * SCAN_B + tid;
    int v = (i < N_NODES) ? g_hist[i] : 0;
    sh[tid] = v;
    __syncthreads();
#pragma unroll
    for (int off = 1; off < SCAN_B; off <<= 1) {
        int t = (tid >= off) ? sh[tid - off] : 0;
        __syncthreads();
        sh[tid] += t;
        __syncthreads();
    }
    if (i < N_NODES) g_start[i] = sh[tid] - v;
    if (tid == SCAN_B - 1) g_blocksum[blockIdx.x] = sh[tid];
}

__global__ void scan2_kernel()
{
    int run = 0;
#pragma unroll 1
    for (int b = 0; b < SCAN_NBLK; ++b) {
        g_blockoff[b] = run;
        run += g_blocksum[b];
    }
}

// ---------------------------------------------------------------------------
__global__ __launch_bounds__(256) void scatter_kernel(const void* __restrict__ ei)
{
    int q = blockIdx.x * blockDim.x + threadIdx.x;
    if (q >= E_EDGES / 2) return;
    int src0, src1, dst0, dst1;
    if (g_idx64) {
        const longlong2* p = (const longlong2*)ei;
        longlong2 sv = __ldg(p + q);
        longlong2 dv = __ldg(p + E_EDGES / 2 + q);
        src0 = (int)sv.x; src1 = (int)sv.y;
        dst0 = (int)dv.x; dst1 = (int)dv.y;
    } else {
        const int2* p = (const int2*)ei;
        int2 sv = __ldg(p + q);
        int2 dv = __ldg(p + E_EDGES / 2 + q);
        src0 = sv.x; src1 = sv.y;
        dst0 = dv.x; dst1 = dv.y;
    }

    float z0 = __ldg(g_s + src0) + __ldg(g_t + dst0);
    float z1 = __ldg(g_s + src1) + __ldg(g_t + dst1);
    float w0 = __expf((z0 > 0.0f) ? z0 : LRELU_ALPHA * z0);
    float w1 = __expf((z1 > 0.0f) ? z1 : LRELU_ALPHA * z1);

    int p0 = atomicAdd(g_start + src0, 1) + __ldg(g_blockoff + (src0 >> 10));
    int p1 = atomicAdd(g_start + src1, 1) + __ldg(g_blockoff + (src1 >> 10));
    g_sorted[p0] = make_int2(dst0, __float_as_int(w0));
    g_sorted[p1] = make_int2(dst1, __float_as_int(w1));
}

// ---------------------------------------------------------------------------
__device__ __forceinline__ float4 h4_load(int nodeid, int sub) {
    uint2 u = __ldg(reinterpret_cast<const uint2*>(g_h + (size_t)nodeid * OUTC) + sub);
    __half2 p0 = *reinterpret_cast<__half2*>(&u.x);
    __half2 p1 = *reinterpret_cast<__half2*>(&u.y);
    float2 f0 = __half22float2(p0);
    float2 f1 = __half22float2(p1);
    return make_float4(f0.x, f0.y, f1.x, f1.y);
}

__global__ __launch_bounds__(256) void aggregate_kernel(float* __restrict__ out)
{
    int gt = blockIdx.x * blockDim.x + threadIdx.x;
    int node = gt >> 4;
    int sub = gt & 15;
    if (node >= N_NODES) return;

    float z = __ldg(g_s + node) + __ldg(g_t + node);
    float wself = __expf((z > 0.0f) ? z : LRELU_ALPHA * z);

    float4 hv = h4_load(node, sub);
    float4 acc = make_float4(wself * hv.x, wself * hv.y, wself * hv.z, wself * hv.w);
    float es = wself;

    int cnt = __ldg(g_hist + node);
    int base = __ldg(g_start + node) + __ldg(g_blockoff + (node >> 10)) - cnt;

    int j = 0;
#pragma unroll 1
    for (; j + 2 <= cnt; j += 2) {
        int2 m0 = __ldg(g_sorted + base + j);
        int2 m1 = __ldg(g_sorted + base + j + 1);
        float4 v0 = h4_load(m0.x, sub);
        float4 v1 = h4_load(m1.x, sub);
        float w0 = __int_as_float(m0.y);
        float w1 = __int_as_float(m1.y);
        acc.x = fmaf(w0, v0.x, acc.x); acc.y = fmaf(w0, v0.y, acc.y);
        acc.z = fmaf(w0, v0.z, acc.z); acc.w = fmaf(w0, v0.w, acc.w);
        acc.x = fmaf(w1, v1.x, acc.x); acc.y = fmaf(w1, v1.y, acc.y);
        acc.z = fmaf(w1, v1.z, acc.z); acc.w = fmaf(w1, v1.w, acc.w);
        es += w0 + w1;
    }
    if (j < cnt) {
        int2 m0 = __ldg(g_sorted + base + j);
        float4 v0 = h4_load(m0.x, sub);
        float w0 = __int_as_float(m0.y);
        acc.x = fmaf(w0, v0.x, acc.x); acc.y = fmaf(w0, v0.y, acc.y);
        acc.z = fmaf(w0, v0.z, acc.z); acc.w = fmaf(w0, v0.w, acc.w);
        es += w0;
    }

    float inv = 1.0f / es;
    reinterpret_cast<float4*>(out)[(size_t)node * 16 + sub] =
        make_float4(acc.x * inv, acc.y * inv, acc.z * inv, acc.w * inv);
}

// ---------------------------------------------------------------------------
// Fork-join: index chain (detect->hist->scan1->scan2) on a side stream,
// overlapped with pq+gemm on the main stream; join before scatter.
// Streams/events created once on the first (uncaptured) call; the event
// record/wait pattern is the standard graph-capture fork/join and turns
// into graph dependency edges.
// ---------------------------------------------------------------------------
extern "C" void kernel_launch(void* const* d_in, const int* in_sizes, int n_in,
                              void* d_out, int out_size)
{
    const float* x = (const float*)d_in[0];
    const float* W = (const float*)d_in[1];
    const float* a = (const float*)d_in[2];
    const void*  ei = d_in[3];
    float* out = (float*)d_out;

    static cudaStream_t side = nullptr;
    static cudaEvent_t evFork = nullptr, evJoin = nullptr;
    if (side == nullptr) {
        cudaStreamCreateWithFlags(&side, cudaStreamNonBlocking);
        cudaEventCreateWithFlags(&evFork, cudaEventDisableTiming);
        cudaEventCreateWithFlags(&evJoin, cudaEventDisableTiming);
    }

    // Fork the side (index) chain.
    cudaEventRecord(evFork, 0);
    cudaStreamWaitEvent(side, evFork, 0);
    detect_zero_kernel<<<(N_NODES + 255) / 256, 256, 0, side>>>((const int*)ei);
    hist_kernel<<<(E_EDGES / 4 + 255) / 256, 256, 0, side>>>(ei);
    scan1_kernel<<<SCAN_NBLK, SCAN_B, 0, side>>>();
    scan2_kernel<<<1, 1, 0, side>>>();
    cudaEventRecord(evJoin, side);

    // Main (x) chain.
    pq_kernel<<<1, 128>>>(W, a);
    gemm_kernel<<<(N_NODES + MBLK - 1) / MBLK, GEMM_THREADS>>>(x, W);

    // Join, then the edge phase.
    cudaStreamWaitEvent(0, evJoin, 0);
    scatter_kernel<<<(E_EDGES / 2 + 255) / 256, 256>>>(ei);
    aggregate_kernel<<<(N_NODES * 16 + 255) / 256, 256>>>(out);
}